// round 5
// baseline (speedup 1.0000x reference)
#include <cuda_runtime.h>
#include <cstdint>

// features: [B=16, H=128, W=128, D=8, F=16] float32, row-major.
// out[b,h,w,d,f] = valid(i,j) ? in[b, si(i,j), sj(i,j), 7-d, f] : 0
//   i = (h-5) mod 128, j = (134-w) mod 128
//   (si,sj) = round_ne( Rinv * (i-63.5, j-63.5) + 63.5 ), Rinv for +40 deg.
//
// One thread = one float4 lane within a 512B (d,f) chunk, for ALL 16 batches.
// Rotation/flip/roll index math computed exactly once per (h,w,lane).
// 16 independent loads (input ~fully L2-resident across replays), then 16
// streaming stores (evict-first, so the write stream doesn't evict the input).

#define ILP 16

__global__ __launch_bounds__(128) void Augment_70566312673947_kernel(
    const float4* __restrict__ in, float4* __restrict__ out)
{
    const float c = 0.76604443f;   // cos(40deg) rounded to f32
    const float s = 0.64278761f;   // sin(40deg) rounded to f32

    int tid = blockIdx.x * blockDim.x + threadIdx.x;   // 0 .. 524,287
    int lane  = tid & 31;          // float4 index within 512B chunk
    int chunk = tid >> 5;          // h*W + w   (0 .. 16383)

    int w = chunk & 127;
    int h = chunk >> 7;

    // roll^-1 then flip-W composed
    int i = h - 5; if (i < 0) i += 128;
    int j = (134 - w) & 127;

    // inverse rotation (f32 ops kept un-fused to match XLA f32 math)
    float fi = (float)i - 63.5f;
    float fj = (float)j - 63.5f;
    float src_i = __fadd_rn(__fadd_rn(__fmul_rn(c, fi), __fmul_rn(s, fj)), 63.5f);
    float src_j = __fadd_rn(__fadd_rn(__fmul_rn(-s, fi), __fmul_rn(c, fj)), 63.5f);
    int si = __float2int_rn(src_i);   // round-half-to-even == jnp.round
    int sj = __float2int_rn(src_j);
    bool valid = (si >= 0) && (si < 128) && (sj >= 0) && (sj < 128);

    // flip D: out granule lane=(d*4+f4) reads src granule ((7-d)*4+f4)
    int d  = lane >> 2;
    int f4 = lane & 3;
    int srclane = ((7 - d) << 2) | f4;

    const size_t bstride = 128u * 128u * 32u;   // one batch, in float4 units

    float4 v[ILP];
#pragma unroll
    for (int u = 0; u < ILP; u++)
        v[u] = make_float4(0.f, 0.f, 0.f, 0.f);

    if (valid) {
        size_t src0 = (((size_t)si * 128 + sj) * 32) + srclane;
#pragma unroll
        for (int u = 0; u < ILP; u++)
            v[u] = __ldg(&in[src0 + (size_t)u * bstride]);
    }

#pragma unroll
    for (int u = 0; u < ILP; u++)
        __stcs(&out[(size_t)tid + (size_t)u * bstride], v[u]);
}

extern "C" void kernel_launch(void* const* d_in, const int* in_sizes, int n_in,
                              void* d_out, int out_size)
{
    const float4* in  = (const float4*)d_in[0];
    float4*       out = (float4*)d_out;
    // total float4 = 8,388,608; each thread writes ILP=16
    int total_threads = (out_size / 4) / ILP;   // 524,288
    int threads = 128;
    int blocks = total_threads / threads;       // 4096
    Augment_70566312673947_kernel<<<blocks, threads>>>(in, out);
}

// round 16
// speedup vs baseline: 1.0073x; 1.0073x over previous
#include <cuda_runtime.h>
#include <cstdint>

// features: [B=16, H=128, W=128, D=8, F=16] float32, row-major.
// out[b,h,w,d,f] = valid(i,j) ? in[b, si(i,j), sj(i,j), 7-d, f] : 0
//   i = (h-5) mod 128, j = (134-w) mod 128
//   (si,sj) = round_ne( Rinv * (i-63.5, j-63.5) + 63.5 ), Rinv for +40 deg.
//
// One thread = one 32B granule (2 float4 = 8 floats) within a 512B (d,f)
// chunk, for 8 batches. 256-bit LDG/STG with L2 policy split: input loads
// evict_last (input ~fits in 126MB L2, re-read every replay), output stores
// evict_first (never re-read). The d-flip maps 32B granule (d,f4pair) to
// (7-d,f4pair): alignment preserved.

#define ILP 8

struct V8 { unsigned r0,r1,r2,r3,r4,r5,r6,r7; };

__device__ __forceinline__ V8 ldg256_evict_last(const void* p) {
    V8 v;
    asm volatile("ld.global.nc.L2::evict_last.v8.b32 {%0,%1,%2,%3,%4,%5,%6,%7}, [%8];"
                 : "=r"(v.r0), "=r"(v.r1), "=r"(v.r2), "=r"(v.r3),
                   "=r"(v.r4), "=r"(v.r5), "=r"(v.r6), "=r"(v.r7)
                 : "l"(p));
    return v;
}

__device__ __forceinline__ void stg256_evict_first(void* p, V8 v) {
    asm volatile("st.global.L2::evict_first.v8.b32 [%0], {%1,%2,%3,%4,%5,%6,%7,%8};"
                 :: "l"(p),
                    "r"(v.r0), "r"(v.r1), "r"(v.r2), "r"(v.r3),
                    "r"(v.r4), "r"(v.r5), "r"(v.r6), "r"(v.r7)
                 : "memory");
}

__global__ __launch_bounds__(256) void Augment_70566312673947_kernel(
    const char* __restrict__ in, char* __restrict__ out)
{
    const float c = 0.76604443f;   // cos(40deg) rounded to f32
    const float s = 0.64278761f;   // sin(40deg) rounded to f32

    int tid = blockIdx.x * blockDim.x + threadIdx.x;   // 0 .. 524,287
    int lane  = tid & 15;          // 32B granule index within 512B chunk
    int chunk = tid >> 4;          // b0*H*W + h*W + w, b0 in [0,2)

    int w = chunk & 127;
    int h = (chunk >> 7) & 127;

    // roll^-1 then flip-W composed
    int i = h - 5; if (i < 0) i += 128;
    int j = (134 - w) & 127;

    // inverse rotation (f32 ops kept un-fused to match XLA f32 math)
    float fi = (float)i - 63.5f;
    float fj = (float)j - 63.5f;
    float src_i = __fadd_rn(__fadd_rn(__fmul_rn(c, fi), __fmul_rn(s, fj)), 63.5f);
    float src_j = __fadd_rn(__fadd_rn(__fmul_rn(-s, fi), __fmul_rn(c, fj)), 63.5f);
    int si = __float2int_rn(src_i);   // round-half-to-even == jnp.round
    int sj = __float2int_rn(src_j);
    bool valid = (si >= 0) && (si < 128) && (sj >= 0) && (sj < 128);

    // flip D on 32B granules: lane = d*2 + fp  ->  src granule (7-d)*2 + fp
    int d  = lane >> 1;
    int fp = lane & 1;
    int srclane = ((7 - d) << 1) | fp;

    // batch stride (2 batches apart) in bytes
    const size_t bstride = 2u * 128u * 128u * 512u;   // 16 MiB

    V8 v[ILP];
#pragma unroll
    for (int u = 0; u < ILP; u++)
        v[u].r0 = v[u].r1 = v[u].r2 = v[u].r3 =
        v[u].r4 = v[u].r5 = v[u].r6 = v[u].r7 = 0u;

    if (valid) {
        // src byte offset for batch b0: ((b0*128+si)*128+sj)*512 + srclane*32
        size_t src0 = (((size_t)si * 128 + sj) * 512) + ((size_t)srclane << 5)
                    + (size_t)(chunk >> 14) * (128u * 128u * 512u);
#pragma unroll
        for (int u = 0; u < ILP; u++)
            v[u] = ldg256_evict_last(in + src0 + (size_t)u * bstride);
    }

    size_t dst0 = (size_t)tid << 5;
#pragma unroll
    for (int u = 0; u < ILP; u++)
        stg256_evict_first(out + dst0 + (size_t)u * bstride, v[u]);
}

extern "C" void kernel_launch(void* const* d_in, const int* in_sizes, int n_in,
                              void* d_out, int out_size)
{
    const char* in  = (const char*)d_in[0];
    char*       out = (char*)d_out;
    // total 32B granules = 16*128*128*512B / 32B = 4,194,304; ILP=8 each
    int total_threads = (out_size / 8) / ILP;   // out_size=33,554,432 floats -> 524,288
    int threads = 256;
    int blocks = total_threads / threads;       // 2048
    Augment_70566312673947_kernel<<<blocks, threads>>>(in, out);
}